// round 1
// baseline (speedup 1.0000x reference)
#include <cuda_runtime.h>

// Problem constants (fixed by the reference: B=8, N=M=4096, C=3)
#define BATCH   8
#define NPTS    4096
#define TILE    1024     // y-points staged in smem per iteration (12 KB)
#define THREADS 128

// Scratch for per-point nearest-neighbor distances (no device allocs allowed)
__device__ float g_min_x[BATCH * NPTS];
__device__ float g_min_y[BATCH * NPTS];

// One thread = one query point of set A; loops over all points of set B (same
// batch) staged through shared memory in TILE-sized chunks.
// blockIdx.z = 0: A=x, B=y (writes g_min_x); z=1: A=y, B=x (writes g_min_y).
__global__ __launch_bounds__(THREADS)
void chamfer_pass_kernel(const float* __restrict__ x,
                         const float* __restrict__ y) {
    __shared__ float sh[TILE * 3];

    const int b   = blockIdx.y;
    const int dir = blockIdx.z;
    const float* A    = dir == 0 ? x : y;
    const float* Bset = dir == 0 ? y : x;
    float* outm       = dir == 0 ? g_min_x : g_min_y;

    const int i = blockIdx.x * THREADS + threadIdx.x;   // query point index
    const float* Ab = A    + (size_t)b * NPTS * 3;
    const float* Bb = Bset + (size_t)b * NPTS * 3;

    const float x0 = Ab[i * 3 + 0];
    const float x1 = Ab[i * 3 + 1];
    const float x2 = Ab[i * 3 + 2];

    // 4 rotating accumulators: breaks the serial FMNMX dependency chain
    float m0 = 1e30f, m1 = 1e30f, m2 = 1e30f, m3 = 1e30f;

    for (int t = 0; t < NPTS; t += TILE) {
        __syncthreads();
        // Cooperative tile load: TILE*3 floats = 768 float4 (16B-aligned:
        // base is cudaMalloc'd, offset t*3*4B is a multiple of 16).
        {
            const float4* src = (const float4*)(Bb + t * 3);
            float4*       dst = (float4*)sh;
            #pragma unroll
            for (int k = threadIdx.x; k < TILE * 3 / 4; k += THREADS)
                dst[k] = src[k];
        }
        __syncthreads();

        #pragma unroll 2
        for (int j = 0; j < TILE; j += 4) {
            const float* p = sh + 3 * j;
            // All lanes read the same addresses -> smem broadcast, no conflicts
            float a0 = p[0],  a1 = p[1],  a2 = p[2];
            float b0 = p[3],  b1 = p[4],  b2 = p[5];
            float c0 = p[6],  c1 = p[7],  c2 = p[8];
            float e0 = p[9],  e1 = p[10], e2 = p[11];

            // fabsf folds into FADD operand |.| modifiers: 5 FADD + 1 FMNMX / pair
            float d0 = fabsf(x0 - a0) + fabsf(x1 - a1) + fabsf(x2 - a2);
            float d1 = fabsf(x0 - b0) + fabsf(x1 - b1) + fabsf(x2 - b2);
            float d2 = fabsf(x0 - c0) + fabsf(x1 - c1) + fabsf(x2 - c2);
            float d3 = fabsf(x0 - e0) + fabsf(x1 - e1) + fabsf(x2 - e2);

            m0 = fminf(m0, d0);
            m1 = fminf(m1, d1);
            m2 = fminf(m2, d2);
            m3 = fminf(m3, d3);
        }
    }

    outm[b * NPTS + i] = fminf(fminf(m0, m1), fminf(m2, m3));
}

// Single-block reduction: result = mean(g_min_x) + mean(g_min_y).
// (point_reduction='mean' then batch_reduction='mean' with uniform sizes
//  collapses to a flat mean over B*N elements per direction.)
__global__ void chamfer_reduce_kernel(float* __restrict__ out) {
    __shared__ float warp_s[32];
    const int tid = threadIdx.x;

    float s = 0.0f;
    for (int k = tid; k < BATCH * NPTS; k += blockDim.x)
        s += g_min_x[k] + g_min_y[k];

    #pragma unroll
    for (int o = 16; o > 0; o >>= 1)
        s += __shfl_down_sync(0xffffffffu, s, o);
    if ((tid & 31) == 0) warp_s[tid >> 5] = s;
    __syncthreads();

    if (tid < 32) {
        float v = (tid < (int)(blockDim.x >> 5)) ? warp_s[tid] : 0.0f;
        #pragma unroll
        for (int o = 16; o > 0; o >>= 1)
            v += __shfl_down_sync(0xffffffffu, v, o);
        if (tid == 0)
            out[0] = v * (1.0f / (float)(BATCH * NPTS));
    }
}

extern "C" void kernel_launch(void* const* d_in, const int* in_sizes, int n_in,
                              void* d_out, int out_size) {
    const float* x = (const float*)d_in[0];
    const float* y = (const float*)d_in[1];
    float* out = (float*)d_out;

    (void)in_sizes; (void)n_in; (void)out_size;

    // Both directions in one grid so they overlap on the chip:
    // grid = (4096/128, 8 batches, 2 directions) = 512 blocks.
    dim3 grid(NPTS / THREADS, BATCH, 2);
    chamfer_pass_kernel<<<grid, THREADS>>>(x, y);
    chamfer_reduce_kernel<<<1, 1024>>>(out);
}